// round 1
// baseline (speedup 1.0000x reference)
#include <cuda_runtime.h>
#include <math.h>

// Problem constants
#define BSZ 8
#define HH 256
#define WW 256
#define C1 64
#define NBR 6

// Scratch: weighted neighbor frames (B, 6, H, W) = 12.6 MB
__device__ float g_weighted[BSZ * NBR * HH * WW];

// Tile geometry: 256 threads, 16x16 thread grid, 4 px/thread in x
#define TW 64
#define TH 16

// ---------------------------------------------------------------------------
// Kernel A: fused  conv1(2->64,3x3) + ReLU + conv2(64->1,1x1) + sigmoid
//           + gate * check  ->  g_weighted
// One block = one (batch, neighbor, 64x16 tile).
// Hidden 64 channels are reduced on the fly (never stored).
// ---------------------------------------------------------------------------
__global__ __launch_bounds__(256, 2) void branch_kernel(
    const float* __restrict__ x,
    const float* __restrict__ W1,
    const float* __restrict__ b1,
    const float* __restrict__ W2,
    const float* __restrict__ b2)
{
    __shared__ float sB[TH + 2][TW + 4];   // base tile + halo (pad to 68)
    __shared__ float sC[TH + 2][TW + 4];   // check tile + halo
    __shared__ float sW1b[C1][9];          // conv1 weights applied to base
    __shared__ float sW1c[C1][9];          // conv1 weights applied to check
    __shared__ float sB1[C1];
    __shared__ float sW2[C1];

    const int bz  = blockIdx.z;
    const int b   = bz / NBR;
    const int n   = bz % NBR;
    const int ty0 = blockIdx.y * TH;
    const int tx0 = blockIdx.x * TW;
    const int tid = threadIdx.x;

    // neighbor n maps to x channel (skip center=3)
    const int checkCh = (n < 3) ? n : (n + 1);
    // pair channel order: n<3 -> (base, check); n>=3 -> (check, base)
    const int bi = (n < 3) ? 0 : 1;

    const float* __restrict__ base = x + (size_t)(b * 7 + 3) * (HH * WW);
    const float* __restrict__ chk  = x + (size_t)(b * 7 + checkCh) * (HH * WW);

    // Stage conv1 weights, split by which pair-channel they multiply
    for (int i = tid; i < C1 * 9; i += 256) {
        int c = i / 9, k = i % 9;
        sW1b[c][k] = W1[((n * C1 + c) * 2 + bi) * 9 + k];
        sW1c[c][k] = W1[((n * C1 + c) * 2 + (1 - bi)) * 9 + k];
    }
    if (tid < C1) {
        sB1[tid] = b1[n * C1 + tid];
        sW2[tid] = W2[n * C1 + tid];
    }

    // Stage input tiles with 1-px zero halo
    for (int i = tid; i < (TH + 2) * (TW + 2); i += 256) {
        int r  = i / (TW + 2);
        int cc = i % (TW + 2);
        int gy = ty0 + r - 1;
        int gx = tx0 + cc - 1;
        bool ok = (gy >= 0) && (gy < HH) && (gx >= 0) && (gx < WW);
        sB[r][cc] = ok ? base[gy * WW + gx] : 0.0f;
        sC[r][cc] = ok ? chk[gy * WW + gx] : 0.0f;
    }
    __syncthreads();

    const int lx = tid & 15;
    const int ly = tid >> 4;
    const int px = lx * 4;          // local col of first pixel

    // Register-resident taps: 3 rows x 6 cols covering 4 adjacent output px
    float tB[18], tC[18];
#pragma unroll
    for (int r = 0; r < 3; r++)
#pragma unroll
        for (int c6 = 0; c6 < 6; c6++) {
            tB[r * 6 + c6] = sB[ly + r][px + c6];
            tC[r * 6 + c6] = sC[ly + r][px + c6];
        }

    float s0 = 0.f, s1 = 0.f, s2 = 0.f, s3 = 0.f;

#pragma unroll 2
    for (int c = 0; c < C1; c++) {
        const float bb = sB1[c];
        float a0 = bb, a1 = bb, a2 = bb, a3 = bb;
#pragma unroll
        for (int r = 0; r < 3; r++)
#pragma unroll
            for (int k = 0; k < 3; k++) {
                const float wb = sW1b[c][r * 3 + k];
                const float wc = sW1c[c][r * 3 + k];
                a0 = fmaf(wb, tB[r * 6 + k],     fmaf(wc, tC[r * 6 + k],     a0));
                a1 = fmaf(wb, tB[r * 6 + k + 1], fmaf(wc, tC[r * 6 + k + 1], a1));
                a2 = fmaf(wb, tB[r * 6 + k + 2], fmaf(wc, tC[r * 6 + k + 2], a2));
                a3 = fmaf(wb, tB[r * 6 + k + 3], fmaf(wc, tC[r * 6 + k + 3], a3));
            }
        const float w2c = sW2[c];
        s0 = fmaf(w2c, fmaxf(a0, 0.f), s0);
        s1 = fmaf(w2c, fmaxf(a1, 0.f), s1);
        s2 = fmaf(w2c, fmaxf(a2, 0.f), s2);
        s3 = fmaf(w2c, fmaxf(a3, 0.f), s3);
    }

    const float bb2 = b2[n];
    const float g0 = 1.f / (1.f + __expf(-(s0 + bb2)));
    const float g1 = 1.f / (1.f + __expf(-(s1 + bb2)));
    const float g2 = 1.f / (1.f + __expf(-(s2 + bb2)));
    const float g3 = 1.f / (1.f + __expf(-(s3 + bb2)));

    const int gy = ty0 + ly;
    float* o = g_weighted + ((size_t)(b * NBR + n) * HH + gy) * WW + tx0 + px;
    float4 w4;
    w4.x = g0 * tC[7];   // center tap of pixel p is tC[1*6 + p + 1]
    w4.y = g1 * tC[8];
    w4.z = g2 * tC[9];
    w4.w = g3 * tC[10];
    *reinterpret_cast<float4*>(o) = w4;
}

// ---------------------------------------------------------------------------
// Kernel B: final 7->7 3x3 conv over [weighted(0..2), base, weighted(3..5)]
// ---------------------------------------------------------------------------
__global__ __launch_bounds__(256, 2) void merge_kernel(
    const float* __restrict__ x,
    const float* __restrict__ Wm,
    const float* __restrict__ bm,
    float* __restrict__ out)
{
    __shared__ float sIn[7][TH + 2][TW + 4];
    __shared__ float sW[7 * 7 * 9];
    __shared__ float sbm[7];

    const int b   = blockIdx.z;
    const int ty0 = blockIdx.y * TH;
    const int tx0 = blockIdx.x * TW;
    const int tid = threadIdx.x;

    for (int i = tid; i < 7 * 7 * 9; i += 256) sW[i] = Wm[i];
    if (tid < 7) sbm[tid] = bm[tid];

    const int tile = (TH + 2) * (TW + 2);
    for (int i = tid; i < 7 * tile; i += 256) {
        int ch  = i / tile;
        int rem = i % tile;
        int r   = rem / (TW + 2);
        int cc  = rem % (TW + 2);
        int gy  = ty0 + r - 1;
        int gx  = tx0 + cc - 1;
        float v = 0.f;
        if (gy >= 0 && gy < HH && gx >= 0 && gx < WW) {
            if (ch == 3) {
                v = x[(size_t)(b * 7 + 3) * (HH * WW) + gy * WW + gx];
            } else {
                int m = (ch < 3) ? ch : (ch - 1);
                v = g_weighted[((size_t)(b * NBR + m) * HH + gy) * WW + gx];
            }
        }
        sIn[ch][r][cc] = v;
    }
    __syncthreads();

    const int lx = tid & 15;
    const int ly = tid >> 4;
    const int px = lx * 4;

    float acc[7][4];
#pragma unroll
    for (int co = 0; co < 7; co++) {
        const float bv = sbm[co];
        acc[co][0] = bv; acc[co][1] = bv; acc[co][2] = bv; acc[co][3] = bv;
    }

#pragma unroll
    for (int ci = 0; ci < 7; ci++) {
        float t[18];
#pragma unroll
        for (int r = 0; r < 3; r++)
#pragma unroll
            for (int c6 = 0; c6 < 6; c6++)
                t[r * 6 + c6] = sIn[ci][ly + r][px + c6];

#pragma unroll
        for (int co = 0; co < 7; co++) {
#pragma unroll
            for (int r = 0; r < 3; r++)
#pragma unroll
                for (int k = 0; k < 3; k++) {
                    const float w = sW[(co * 7 + ci) * 9 + r * 3 + k];
                    acc[co][0] = fmaf(w, t[r * 6 + k],     acc[co][0]);
                    acc[co][1] = fmaf(w, t[r * 6 + k + 1], acc[co][1]);
                    acc[co][2] = fmaf(w, t[r * 6 + k + 2], acc[co][2]);
                    acc[co][3] = fmaf(w, t[r * 6 + k + 3], acc[co][3]);
                }
        }
    }

    const int gy = ty0 + ly;
#pragma unroll
    for (int co = 0; co < 7; co++) {
        float* o = out + ((size_t)(b * 7 + co) * HH + gy) * WW + tx0 + px;
        float4 v4;
        v4.x = acc[co][0]; v4.y = acc[co][1]; v4.z = acc[co][2]; v4.w = acc[co][3];
        *reinterpret_cast<float4*>(o) = v4;
    }
}

// ---------------------------------------------------------------------------
extern "C" void kernel_launch(void* const* d_in, const int* in_sizes, int n_in,
                              void* d_out, int out_size)
{
    const float* x  = (const float*)d_in[0];   // (8, 7, 256, 256)
    const float* W1 = (const float*)d_in[1];   // (6, 64, 2, 3, 3)
    const float* b1 = (const float*)d_in[2];   // (6, 64)
    const float* W2 = (const float*)d_in[3];   // (6, 1, 64, 1, 1)
    const float* b2 = (const float*)d_in[4];   // (6, 1)
    const float* Wm = (const float*)d_in[5];   // (7, 7, 3, 3)
    const float* bm = (const float*)d_in[6];   // (7,)

    dim3 grid1(WW / TW, HH / TH, BSZ * NBR);   // 4 x 16 x 48
    branch_kernel<<<grid1, 256>>>(x, W1, b1, W2, b2);

    dim3 grid2(WW / TW, HH / TH, BSZ);         // 4 x 16 x 8
    merge_kernel<<<grid2, 256>>>(x, Wm, bm, (float*)d_out);
}